// round 9
// baseline (speedup 1.0000x reference)
#include <cuda_runtime.h>
#include <cuda_bf16.h>
#include <math.h>
#include <stdint.h>

#define BSZ 4
#define SEQ 2048
#define DMODEL 1024
#define NHEADS 8
#define DH 128
#define NEG_INF -1e9f

// ===================== static device scratch =====================
__device__ float  g_Q[BSZ * NHEADS * SEQ * DH];
__device__ float  g_K[BSZ * NHEADS * SEQ * DH];
__device__ float  g_V[BSZ * NHEADS * SEQ * DH];
__device__ float  g_AP[SEQ * SEQ];
__device__ float2 g_stats[BSZ * NHEADS * SEQ];     // (rowmax, sumexp) per (bh, j)
__device__ float  g_Y[BSZ * SEQ * DMODEL];

// ===================== helpers =====================
__device__ __forceinline__ uint32_t smem_u32(const void* p) {
    uint32_t a;
    asm("{ .reg .u64 t; cvta.to.shared.u64 t, %1; cvt.u32.u64 %0, t; }" : "=r"(a) : "l"(p));
    return a;
}
__device__ __forceinline__ void ldsm4(uint32_t* r, uint32_t addr) {
    asm volatile("ldmatrix.sync.aligned.m8n8.x4.shared.b16 {%0,%1,%2,%3}, [%4];"
        : "=r"(r[0]), "=r"(r[1]), "=r"(r[2]), "=r"(r[3]) : "r"(addr));
}
__device__ __forceinline__ void ldsm4_t(uint32_t* r, uint32_t addr) {
    asm volatile("ldmatrix.sync.aligned.m8n8.x4.trans.shared.b16 {%0,%1,%2,%3}, [%4];"
        : "=r"(r[0]), "=r"(r[1]), "=r"(r[2]), "=r"(r[3]) : "r"(addr));
}
__device__ __forceinline__ void mma16816(float* c, const uint32_t* a, uint32_t b0, uint32_t b1) {
    asm volatile("mma.sync.aligned.m16n8k16.row.col.f32.bf16.bf16.f32 "
        "{%0,%1,%2,%3}, {%4,%5,%6,%7}, {%8,%9}, {%0,%1,%2,%3};"
        : "+f"(c[0]), "+f"(c[1]), "+f"(c[2]), "+f"(c[3])
        : "r"(a[0]), "r"(a[1]), "r"(a[2]), "r"(a[3]), "r"(b0), "r"(b1));
}
__device__ __forceinline__ void split4(float4 v, uint2& hi, uint2& lo) {
    __nv_bfloat162 h0 = __floats2bfloat162_rn(v.x, v.y);
    __nv_bfloat162 h1 = __floats2bfloat162_rn(v.z, v.w);
    __nv_bfloat162 l0 = __floats2bfloat162_rn(v.x - __bfloat162float(h0.x),
                                              v.y - __bfloat162float(h0.y));
    __nv_bfloat162 l1 = __floats2bfloat162_rn(v.z - __bfloat162float(h1.x),
                                              v.w - __bfloat162float(h1.y));
    hi.x = *(uint32_t*)&h0; hi.y = *(uint32_t*)&h1;
    lo.x = *(uint32_t*)&l0; lo.y = *(uint32_t*)&l1;
}
__device__ __forceinline__ uint32_t split2(float a, float b, uint32_t& lo) {
    __nv_bfloat162 h = __floats2bfloat162_rn(a, b);
    __nv_bfloat162 l = __floats2bfloat162_rn(a - __bfloat162float(h.x),
                                             b - __bfloat162float(h.y));
    lo = *(uint32_t*)&l;
    return *(uint32_t*)&h;
}

// ===================== NT mainloop (A[m][k], B[n][k], fp32 -> bf16x3 mma) ==============
// smem stage: Ahi@0 Alo@10240 Bhi@20480 Blo@30720 ; rows padded to 80B ; 2 stages
#define NT_STAGE 40960
#define NT_SMEM (2 * NT_STAGE)

__device__ __forceinline__ void gemm_nt_mma(
    const float* __restrict__ Ag, int lda,
    const float* __restrict__ Bg, int ldb,
    int K, char* sm, float (&acc)[4][4][4])
{
    const int tid = threadIdx.x, lane = tid & 31, wid = tid >> 5;
    const int morg = (wid >> 2) * 64, norg = (wid & 3) * 32;
    const int lr = tid >> 3, lc = (tid & 7) << 2;
    const uint32_t sbase = smem_u32(sm);
    const int nc = K / 32;
    float4 va[4], vb[4];

    #pragma unroll
    for (int rb = 0; rb < 4; rb++) {
        va[rb] = *(const float4*)(Ag + (size_t)(lr + rb * 32) * lda + lc);
        vb[rb] = *(const float4*)(Bg + (size_t)(lr + rb * 32) * ldb + lc);
    }
    {
        char* st = sm;
        #pragma unroll
        for (int rb = 0; rb < 4; rb++) {
            uint2 hi, lo;
            int off = (lr + rb * 32) * 80 + lc * 2;
            split4(va[rb], hi, lo);
            *(uint2*)(st + off) = hi; *(uint2*)(st + 10240 + off) = lo;
            split4(vb[rb], hi, lo);
            *(uint2*)(st + 20480 + off) = hi; *(uint2*)(st + 30720 + off) = lo;
        }
    }

    for (int c = 0; c < nc; c++) {
        __syncthreads();
        if (c + 1 < nc) {
            #pragma unroll
            for (int rb = 0; rb < 4; rb++) {
                va[rb] = *(const float4*)(Ag + (size_t)(lr + rb * 32) * lda + (c + 1) * 32 + lc);
                vb[rb] = *(const float4*)(Bg + (size_t)(lr + rb * 32) * ldb + (c + 1) * 32 + lc);
            }
        }
        const uint32_t sst = sbase + (c & 1) * NT_STAGE;
        #pragma unroll
        for (int kh = 0; kh < 2; kh++) {
            uint32_t Ah[4][4], Al[4][4], Bh[2][4], Bl[2][4];
            #pragma unroll
            for (int mf = 0; mf < 4; mf++) {
                uint32_t r = morg + mf * 16 + (lane & 15);
                uint32_t ad = sst + r * 80 + ((lane >> 4) << 4) + kh * 32;
                ldsm4(Ah[mf], ad);
                ldsm4(Al[mf], ad + 10240);
            }
            #pragma unroll
            for (int nb = 0; nb < 2; nb++) {
                uint32_t r = norg + nb * 16 + (lane & 7) + ((lane >> 4) << 3);
                uint32_t ad = sst + 20480 + r * 80 + (((lane >> 3) & 1) << 4) + kh * 32;
                ldsm4(Bh[nb], ad);
                ldsm4(Bl[nb], ad + 10240);
            }
            #pragma unroll
            for (int mf = 0; mf < 4; mf++)
                #pragma unroll
                for (int j = 0; j < 4; j++) {
                    uint32_t b0h = Bh[j >> 1][(j & 1) * 2], b1h = Bh[j >> 1][(j & 1) * 2 + 1];
                    uint32_t b0l = Bl[j >> 1][(j & 1) * 2], b1l = Bl[j >> 1][(j & 1) * 2 + 1];
                    mma16816(acc[mf][j], Ah[mf], b0h, b1h);
                    mma16816(acc[mf][j], Ah[mf], b0l, b1l);
                    mma16816(acc[mf][j], Al[mf], b0h, b1h);
                }
        }
        __syncthreads();
        if (c + 1 < nc) {
            char* st = sm + ((c + 1) & 1) * NT_STAGE;
            #pragma unroll
            for (int rb = 0; rb < 4; rb++) {
                uint2 hi, lo;
                int off = (lr + rb * 32) * 80 + lc * 2;
                split4(va[rb], hi, lo);
                *(uint2*)(st + off) = hi; *(uint2*)(st + 10240 + off) = lo;
                split4(vb[rb], hi, lo);
                *(uint2*)(st + 20480 + off) = hi; *(uint2*)(st + 30720 + off) = lo;
            }
        }
    }
}

// ===================== proj / outproj =====================
__global__ void __launch_bounds__(256, 2) proj_kernel(
    const float* __restrict__ x, const float* __restrict__ W, float* __restrict__ outp)
{
    extern __shared__ char sm[];
    float acc[4][4][4] = {};
    const int tileM = blockIdx.y * 128, tileN = blockIdx.x * 128;
    gemm_nt_mma(x + (size_t)tileM * DMODEL, DMODEL,
                W + (size_t)tileN * DMODEL, DMODEL, DMODEL, sm, acc);

    const int lane = threadIdx.x & 31, wid = threadIdx.x >> 5;
    const int h = blockIdx.x;
    #pragma unroll
    for (int mf = 0; mf < 4; mf++) {
        int row = tileM + (wid >> 2) * 64 + mf * 16 + (lane >> 2);
        #pragma unroll
        for (int j = 0; j < 4; j++) {
            int e = (wid & 3) * 32 + j * 8 + (lane & 3) * 2;
            int b0 = row >> 11, ns0 = row & 2047;
            float* d0 = outp + (((size_t)(b0 * NHEADS + h) * SEQ + ns0) * DH + e);
            *(float2*)d0 = make_float2(acc[mf][j][0], acc[mf][j][1]);
            int r1 = row + 8;
            int b1 = r1 >> 11, ns1 = r1 & 2047;
            float* d1 = outp + (((size_t)(b1 * NHEADS + h) * SEQ + ns1) * DH + e);
            *(float2*)d1 = make_float2(acc[mf][j][2], acc[mf][j][3]);
        }
    }
}

__global__ void __launch_bounds__(256, 2) outproj_kernel(
    const float* __restrict__ Y, const float* __restrict__ Wout, float* __restrict__ out)
{
    extern __shared__ char sm[];
    float acc[4][4][4] = {};
    const int tileM = blockIdx.y * 128, tileN = blockIdx.x * 128;
    gemm_nt_mma(Y + (size_t)tileM * DMODEL, DMODEL,
                Wout + (size_t)tileN * DMODEL, DMODEL, DMODEL, sm, acc);

    const int lane = threadIdx.x & 31, wid = threadIdx.x >> 5;
    #pragma unroll
    for (int mf = 0; mf < 4; mf++) {
        int row = tileM + (wid >> 2) * 64 + mf * 16 + (lane >> 2);
        #pragma unroll
        for (int j = 0; j < 4; j++) {
            int col = tileN + (wid & 3) * 32 + j * 8 + (lane & 3) * 2;
            *(float2*)(out + (size_t)row * DMODEL + col) =
                make_float2(acc[mf][j][0], acc[mf][j][1]);
            *(float2*)(out + (size_t)(row + 8) * DMODEL + col) =
                make_float2(acc[mf][j][2], acc[mf][j][3]);
        }
    }
}

// ===================== pass 1: row stats (online softmax, no S materialization) ==========
__global__ void __launch_bounds__(256, 2) stats_kernel(
    const float* __restrict__ Q, const float* __restrict__ Km,
    const int* __restrict__ mask, const float* __restrict__ AP,
    float2* __restrict__ stats)
{
    extern __shared__ char sm[];
    const int bh = blockIdx.y;
    const int b = bh >> 3;
    const size_t hb = (size_t)bh * SEQ * DH;
    const int j0 = blockIdx.x * 128;

    const int tid = threadIdx.x, lane = tid & 31, wid = tid >> 5;
    const int morg = (wid >> 2) * 64, norg = (wid & 3) * 32;
    const int* mb = mask + b * SEQ;

    float mrow[4][2], srow[4][2];
    #pragma unroll
    for (int mf = 0; mf < 4; mf++) { mrow[mf][0] = mrow[mf][1] = -1e38f; srow[mf][0] = srow[mf][1] = 0.f; }

    for (int it = 0; it < 16; it++) {
        float acc[4][4][4] = {};
        gemm_nt_mma(Q + hb + (size_t)j0 * DH, DH,
                    Km + hb + (size_t)it * 128 * DH, DH, DH, sm, acc);
        #pragma unroll
        for (int mf = 0; mf < 4; mf++) {
            int r0 = morg + mf * 16 + (lane >> 2);
            int r1 = r0 + 8;
            int mr0 = mb[j0 + r0], mr1 = mb[j0 + r1];
            #pragma unroll
            for (int jj = 0; jj < 4; jj++) {
                int gi = it * 128 + norg + jj * 8 + (lane & 3) * 2;
                int mc0 = mb[gi], mc1 = mb[gi + 1];
                const float* ap0 = AP + (size_t)(j0 + r0) * SEQ + gi;
                const float* ap1 = AP + (size_t)(j0 + r1) * SEQ + gi;
                float v00 = (mr0 && mc0) ? acc[mf][jj][0] + ap0[0] : NEG_INF;
                float v01 = (mr0 && mc1) ? acc[mf][jj][1] + ap0[1] : NEG_INF;
                float v10 = (mr1 && mc0) ? acc[mf][jj][2] + ap1[0] : NEG_INF;
                float v11 = (mr1 && mc1) ? acc[mf][jj][3] + ap1[1] : NEG_INF;
                float mn0 = fmaxf(mrow[mf][0], fmaxf(v00, v01));
                srow[mf][0] = srow[mf][0] * __expf(mrow[mf][0] - mn0)
                            + __expf(v00 - mn0) + __expf(v01 - mn0);
                mrow[mf][0] = mn0;
                float mn1 = fmaxf(mrow[mf][1], fmaxf(v10, v11));
                srow[mf][1] = srow[mf][1] * __expf(mrow[mf][1] - mn1)
                            + __expf(v10 - mn1) + __expf(v11 - mn1);
                mrow[mf][1] = mn1;
            }
        }
    }

    // merge within lane quad (lanes sharing a row)
    float2* smst = (float2*)sm;   // [8 warps][64 rows]
    #pragma unroll
    for (int mf = 0; mf < 4; mf++)
        #pragma unroll
        for (int rr = 0; rr < 2; rr++) {
            float mm = mrow[mf][rr], ss = srow[mf][rr];
            #pragma unroll
            for (int dx = 1; dx <= 2; dx <<= 1) {
                float om = __shfl_xor_sync(0xffffffff, mm, dx);
                float os = __shfl_xor_sync(0xffffffff, ss, dx);
                float M = fmaxf(mm, om);
                ss = ss * __expf(mm - M) + os * __expf(om - M);
                mm = M;
            }
            if ((lane & 3) == 0) {
                int rloc = mf * 16 + (lane >> 2) + rr * 8;   // 0..63
                smst[wid * 64 + rloc] = make_float2(mm, ss);
            }
        }
    __syncthreads();
    if (tid < 128) {
        int grp = tid >> 6;       // 0: warps 0-3 (rows 0-63), 1: warps 4-7 (rows 64-127)
        int rl = tid & 63;
        float M = -1e38f, S = 0.f;
        #pragma unroll
        for (int w = 0; w < 4; w++) {
            float2 p = smst[(grp * 4 + w) * 64 + rl];
            float Mn = fmaxf(M, p.x);
            S = S * __expf(M - Mn) + p.y * __expf(p.x - Mn);
            M = Mn;
        }
        stats[(size_t)bh * SEQ + j0 + grp * 64 + rl] = make_float2(M, S);
    }
}

// ===================== pass 2: fused S-recompute + softmax weights + P^T V ==========
// smem: NT stage [0,81920) aliases P/V (phase-disjoint).
// P_hi@0 P_lo@34816 V_hi@69632 V_lo@104448 (128 rows x 272B each); stats@139264
#define PB_LO 34816
#define VB_HI 69632
#define VB_LO 104448
#define ST_OFF 139264
#define AV_SMEM (ST_OFF + 1024)

__global__ void __launch_bounds__(256) av_fused_kernel(
    const float* __restrict__ Q, const float* __restrict__ Km,
    const float* __restrict__ V, const int* __restrict__ mask,
    const float* __restrict__ AP, const float2* __restrict__ stats,
    float* __restrict__ attOut, int hasAtt, float* __restrict__ Y)
{
    extern __shared__ char sm[];
    const uint32_t sbase = smem_u32(sm);
    const int bh = blockIdx.y;
    const int b = bh >> 3, h = bh & 7;
    const size_t hb = (size_t)bh * SEQ * DH;
    const int i0 = blockIdx.x * 128;

    const int tid = threadIdx.x, lane = tid & 31, wid = tid >> 5;
    const int morg = (wid >> 2) * 64, norg = (wid & 3) * 32;
    const int* mb = mask + b * SEQ;
    const float* Vb = V + hb;
    float* attB = attOut + (size_t)b * SEQ * SEQ;

    float yacc[4][4][4] = {};

    for (int jt = 0; jt < 16; jt++) {
        const int j0 = jt * 128;
        // ---- phase A: S tile = Q[j-tile] . K[i-tile]^T ----
        float acc[4][4][4] = {};
        gemm_nt_mma(Q + hb + (size_t)j0 * DH, DH,
                    Km + hb + (size_t)i0 * DH, DH, DH, sm, acc);
        // stats tile for rows j0..j0+127
        if (tid < 128)
            *(float2*)(sm + ST_OFF + tid * 8) = stats[(size_t)bh * SEQ + j0 + tid];
        __syncthreads();

        // ---- phase B: weights -> P (bf16 hi/lo in smem), attOut for h==7; V tile stage ----
        const float2* sstat = (const float2*)(sm + ST_OFF);
        #pragma unroll
        for (int mf = 0; mf < 4; mf++) {
            int r0 = morg + mf * 16 + (lane >> 2);
            int r1 = r0 + 8;
            int mr0 = mb[j0 + r0], mr1 = mb[j0 + r1];
            float2 st0 = sstat[r0], st1 = sstat[r1];
            float inv0 = 1.0f / st0.y, inv1 = 1.0f / st1.y;
            #pragma unroll
            for (int jj = 0; jj < 4; jj++) {
                int cl = norg + jj * 8 + (lane & 3) * 2;     // i-local
                int gi = i0 + cl;
                int mc0 = mb[gi], mc1 = mb[gi + 1];
                const float* ap0 = AP + (size_t)(j0 + r0) * SEQ + gi;
                const float* ap1 = AP + (size_t)(j0 + r1) * SEQ + gi;
                float v00 = (mr0 && mc0) ? acc[mf][jj][0] + ap0[0] : NEG_INF;
                float v01 = (mr0 && mc1) ? acc[mf][jj][1] + ap0[1] : NEG_INF;
                float v10 = (mr1 && mc0) ? acc[mf][jj][2] + ap1[0] : NEG_INF;
                float v11 = (mr1 && mc1) ? acc[mf][jj][3] + ap1[1] : NEG_INF;
                float w00 = __expf(v00 - st0.x) * inv0;
                float w01 = __expf(v01 - st0.x) * inv0;
                float w10 = __expf(v10 - st1.x) * inv1;
                float w11 = __expf(v11 - st1.x) * inv1;
                if (h == 7 && hasAtt) {
                    *(float2*)(attB + (size_t)(j0 + r0) * SEQ + gi) = make_float2(w00, w01);
                    *(float2*)(attB + (size_t)(j0 + r1) * SEQ + gi) = make_float2(w10, w11);
                }
                uint32_t lo0, lo1;
                uint32_t hi0 = split2(w00, w01, lo0);
                uint32_t hi1 = split2(w10, w11, lo1);
                *(uint32_t*)(sm + r0 * 272 + cl * 2) = hi0;
                *(uint32_t*)(sm + PB_LO + r0 * 272 + cl * 2) = lo0;
                *(uint32_t*)(sm + r1 * 272 + cl * 2) = hi1;
                *(uint32_t*)(sm + PB_LO + r1 * 272 + cl * 2) = lo1;
            }
        }
        // V tile stage: rows j-local, 128 cols e
        {
            int vr = tid >> 1;
            int vc = (tid & 1) * 64;
            const float* vsrc = Vb + (size_t)(j0 + vr) * DH + vc;
            char* vh = sm + VB_HI + vr * 272 + vc * 2;
            char* vl = sm + VB_LO + vr * 272 + vc * 2;
            #pragma unroll
            for (int u = 0; u < 16; u++) {
                float4 v = *(const float4*)(vsrc + u * 4);
                uint2 hi, lo;
                split4(v, hi, lo);
                *(uint2*)(vh + u * 8) = hi;
                *(uint2*)(vl + u * 8) = lo;
            }
        }
        __syncthreads();

        // ---- phase C: yacc += P^T V (contraction over j-local = 128) ----
        #pragma unroll
        for (int kc = 0; kc < 4; kc++) {
            #pragma unroll
            for (int kh = 0; kh < 2; kh++) {
                uint32_t Ah[4][4], Al[4][4], Bh[2][4], Bl[2][4];
                #pragma unroll
                for (int mf = 0; mf < 4; mf++) {
                    uint32_t krow = (lane & 7) + ((lane >> 4) << 3) + kh * 16 + kc * 32;
                    uint32_t ad = sbase + krow * 272 + (((lane >> 3) & 1) << 4) + (morg + mf * 16) * 2;
                    ldsm4_t(Ah[mf], ad);
                    ldsm4_t(Al[mf], ad + PB_LO);
                }
                #pragma unroll
                for (int nb = 0; nb < 2; nb++) {
                    uint32_t krow = (lane & 7) + (((lane >> 3) & 1) << 3) + kh * 16 + kc * 32;
                    uint32_t ad = sbase + VB_HI + krow * 272 + ((lane >> 4) << 4) + (norg + nb * 16) * 2;
                    ldsm4_t(Bh[nb], ad);
                    ldsm4_t(Bl[nb], ad + (VB_LO - VB_HI));
                }
                #pragma unroll
                for (int mf = 0; mf < 4; mf++)
                    #pragma unroll
                    for (int j = 0; j < 4; j++) {
                        uint32_t b0h = Bh[j >> 1][(j & 1) * 2], b1h = Bh[j >> 1][(j & 1) * 2 + 1];
                        uint32_t b0l = Bl[j >> 1][(j & 1) * 2], b1l = Bl[j >> 1][(j & 1) * 2 + 1];
                        mma16816(yacc[mf][j], Ah[mf], b0h, b1h);
                        mma16816(yacc[mf][j], Ah[mf], b0l, b1l);
                        mma16816(yacc[mf][j], Al[mf], b0h, b1h);
                    }
            }
        }
        __syncthreads();   // P/V dead before next phase A staging
    }

    // ---- epilogue: write Y[b, i, h*128+e] ----
    #pragma unroll
    for (int mf = 0; mf < 4; mf++) {
        int il = morg + mf * 16 + (lane >> 2);
        int i_g0 = i0 + il, i_g1 = i_g0 + 8;
        #pragma unroll
        for (int j = 0; j < 4; j++) {
            int e = norg + j * 8 + (lane & 3) * 2;
            float* d0 = Y + ((size_t)b * SEQ + i_g0) * DMODEL + h * DH + e;
            float* d1 = Y + ((size_t)b * SEQ + i_g1) * DMODEL + h * DH + e;
            *(float2*)d0 = make_float2(yacc[mf][j][0], yacc[mf][j][1]);
            *(float2*)d1 = make_float2(yacc[mf][j][2], yacc[mf][j][3]);
        }
    }
}

// ===================== AP table =====================
__global__ void ap_kernel(float* __restrict__ AP) {
    int idx = blockIdx.x * blockDim.x + threadIdx.x;
    const int total = SEQ * (SEQ / 2);
    if (idx >= total) return;
    int p = idx / (SEQ / 2);
    int i = idx % (SEQ / 2);
    float denom = powf(10000.0f, (2.0f * (float)i) / 1024.0f);
    float angle = (float)p / denom;
    float s, c;
    sincosf(angle, &s, &c);
    AP[(size_t)p * SEQ + 2 * i]     = s;
    AP[(size_t)p * SEQ + 2 * i + 1] = c;
}

// ===================== launch =====================
extern "C" void kernel_launch(void* const* d_in, const int* in_sizes, int n_in,
                              void* d_out, int out_size) {
    const float* x    = (const float*)d_in[0];
    const int*   mask = (const int*)  d_in[1];
    const float* Wq   = (const float*)d_in[2];
    const float* Wk   = (const float*)d_in[3];
    const float* Wv   = (const float*)d_in[4];
    const float* Wout = (const float*)d_in[5];
    float* out = (float*)d_out;

    const long long outElems = (long long)BSZ * SEQ * DMODEL;
    const long long attElems = (long long)BSZ * SEQ * SEQ;
    int hasAtt = ((long long)out_size >= outElems + attElems) ? 1 : 0;
    float* attOut = out + outElems;

    float *Qp, *Kp, *Vp, *APp, *Yp;
    float2* Sp;
    cudaGetSymbolAddress((void**)&Qp,  g_Q);
    cudaGetSymbolAddress((void**)&Kp,  g_K);
    cudaGetSymbolAddress((void**)&Vp,  g_V);
    cudaGetSymbolAddress((void**)&APp, g_AP);
    cudaGetSymbolAddress((void**)&Sp,  g_stats);
    cudaGetSymbolAddress((void**)&Yp,  g_Y);

    cudaFuncSetAttribute(proj_kernel,     cudaFuncAttributeMaxDynamicSharedMemorySize, NT_SMEM);
    cudaFuncSetAttribute(stats_kernel,    cudaFuncAttributeMaxDynamicSharedMemorySize, NT_SMEM);
    cudaFuncSetAttribute(outproj_kernel,  cudaFuncAttributeMaxDynamicSharedMemorySize, NT_SMEM);
    cudaFuncSetAttribute(av_fused_kernel, cudaFuncAttributeMaxDynamicSharedMemorySize, AV_SMEM);

    // 1. AP table
    {
        int total = SEQ * (SEQ / 2);
        ap_kernel<<<(total + 255) / 256, 256>>>(APp);
    }
    // 2. projections
    {
        dim3 g(DMODEL / 128, (BSZ * SEQ) / 128);
        proj_kernel<<<g, 256, NT_SMEM>>>(x, Wq, Qp);
        proj_kernel<<<g, 256, NT_SMEM>>>(x, Wk, Kp);
        proj_kernel<<<g, 256, NT_SMEM>>>(x, Wv, Vp);
    }
    // 3. softmax row stats (online, no S materialization)
    {
        dim3 g(SEQ / 128, BSZ * NHEADS);
        stats_kernel<<<g, 256, NT_SMEM>>>(Qp, Kp, mask, APp, Sp);
    }
    // 4. fused S-recompute + weights + P^T V (+ attOut for h==7)
    {
        dim3 g(SEQ / 128, BSZ * NHEADS);
        av_fused_kernel<<<g, 256, AV_SMEM>>>(Qp, Kp, Vp, mask, APp, Sp, attOut, hasAtt, Yp);
    }
    // 5. out projection
    {
        dim3 g(DMODEL / 128, (BSZ * SEQ) / 128);
        outproj_kernel<<<g, 256, NT_SMEM>>>(Yp, Wout, out);
    }
}

// round 10
// speedup vs baseline: 1.2927x; 1.2927x over previous
#include <cuda_runtime.h>
#include <cuda_bf16.h>
#include <math.h>
#include <stdint.h>

#define BSZ 4
#define SEQ 2048
#define DMODEL 1024
#define NHEADS 8
#define DH 128
#define NEG_INF -1e9f

// ===================== static device scratch =====================
__device__ float  g_Q[BSZ * NHEADS * SEQ * DH];
__device__ float  g_K[BSZ * NHEADS * SEQ * DH];
__device__ float  g_V[BSZ * NHEADS * SEQ * DH];
__device__ float  g_AP[SEQ * SEQ];
__device__ float  g_A[(size_t)BSZ * NHEADS * SEQ * SEQ];
__device__ float2 g_stats[BSZ * NHEADS * SEQ];
__device__ float  g_Y[BSZ * SEQ * DMODEL];

// ===================== helpers =====================
__device__ __forceinline__ uint32_t smem_u32(const void* p) {
    uint32_t a;
    asm("{ .reg .u64 t; cvta.to.shared.u64 t, %1; cvt.u32.u64 %0, t; }" : "=r"(a) : "l"(p));
    return a;
}
__device__ __forceinline__ void ldsm4(uint32_t* r, uint32_t addr) {
    asm volatile("ldmatrix.sync.aligned.m8n8.x4.shared.b16 {%0,%1,%2,%3}, [%4];"
        : "=r"(r[0]), "=r"(r[1]), "=r"(r[2]), "=r"(r[3]) : "r"(addr));
}
__device__ __forceinline__ void ldsm4_t(uint32_t* r, uint32_t addr) {
    asm volatile("ldmatrix.sync.aligned.m8n8.x4.trans.shared.b16 {%0,%1,%2,%3}, [%4];"
        : "=r"(r[0]), "=r"(r[1]), "=r"(r[2]), "=r"(r[3]) : "r"(addr));
}
__device__ __forceinline__ void mma16816(float* c, const uint32_t* a, uint32_t b0, uint32_t b1) {
    asm volatile("mma.sync.aligned.m16n8k16.row.col.f32.bf16.bf16.f32 "
        "{%0,%1,%2,%3}, {%4,%5,%6,%7}, {%8,%9}, {%0,%1,%2,%3};"
        : "+f"(c[0]), "+f"(c[1]), "+f"(c[2]), "+f"(c[3])
        : "r"(a[0]), "r"(a[1]), "r"(a[2]), "r"(a[3]), "r"(b0), "r"(b1));
}
__device__ __forceinline__ void split4(float4 v, uint2& hi, uint2& lo) {
    __nv_bfloat162 h0 = __floats2bfloat162_rn(v.x, v.y);
    __nv_bfloat162 h1 = __floats2bfloat162_rn(v.z, v.w);
    __nv_bfloat162 l0 = __floats2bfloat162_rn(v.x - __bfloat162float(h0.x),
                                              v.y - __bfloat162float(h0.y));
    __nv_bfloat162 l1 = __floats2bfloat162_rn(v.z - __bfloat162float(h1.x),
                                              v.w - __bfloat162float(h1.y));
    hi.x = *(uint32_t*)&h0; hi.y = *(uint32_t*)&h1;
    lo.x = *(uint32_t*)&l0; lo.y = *(uint32_t*)&l1;
}

// ===================== NT mainloop (A[m][k], B[n][k], fp32 -> bf16x3 mma) ==============
#define NT_STAGE 40960
#define NT_SMEM (2 * NT_STAGE)

__device__ __forceinline__ void gemm_nt_mma(
    const float* __restrict__ Ag, int lda,
    const float* __restrict__ Bg, int ldb,
    int K, char* sm, float (&acc)[4][4][4])
{
    const int tid = threadIdx.x, lane = tid & 31, wid = tid >> 5;
    const int morg = (wid >> 2) * 64, norg = (wid & 3) * 32;
    const int lr = tid >> 3, lc = (tid & 7) << 2;
    const uint32_t sbase = smem_u32(sm);
    const int nc = K / 32;
    float4 va[4], vb[4];

    #pragma unroll
    for (int rb = 0; rb < 4; rb++) {
        va[rb] = *(const float4*)(Ag + (size_t)(lr + rb * 32) * lda + lc);
        vb[rb] = *(const float4*)(Bg + (size_t)(lr + rb * 32) * ldb + lc);
    }
    {
        char* st = sm;
        #pragma unroll
        for (int rb = 0; rb < 4; rb++) {
            uint2 hi, lo;
            int off = (lr + rb * 32) * 80 + lc * 2;
            split4(va[rb], hi, lo);
            *(uint2*)(st + off) = hi; *(uint2*)(st + 10240 + off) = lo;
            split4(vb[rb], hi, lo);
            *(uint2*)(st + 20480 + off) = hi; *(uint2*)(st + 30720 + off) = lo;
        }
    }

    for (int c = 0; c < nc; c++) {
        __syncthreads();
        if (c + 1 < nc) {
            #pragma unroll
            for (int rb = 0; rb < 4; rb++) {
                va[rb] = *(const float4*)(Ag + (size_t)(lr + rb * 32) * lda + (c + 1) * 32 + lc);
                vb[rb] = *(const float4*)(Bg + (size_t)(lr + rb * 32) * ldb + (c + 1) * 32 + lc);
            }
        }
        const uint32_t sst = sbase + (c & 1) * NT_STAGE;
        #pragma unroll
        for (int kh = 0; kh < 2; kh++) {
            uint32_t Ah[4][4], Al[4][4], Bh[2][4], Bl[2][4];
            #pragma unroll
            for (int mf = 0; mf < 4; mf++) {
                uint32_t r = morg + mf * 16 + (lane & 15);
                uint32_t ad = sst + r * 80 + ((lane >> 4) << 4) + kh * 32;
                ldsm4(Ah[mf], ad);
                ldsm4(Al[mf], ad + 10240);
            }
            #pragma unroll
            for (int nb = 0; nb < 2; nb++) {
                uint32_t r = norg + nb * 16 + (lane & 7) + ((lane >> 4) << 3);
                uint32_t ad = sst + 20480 + r * 80 + (((lane >> 3) & 1) << 4) + kh * 32;
                ldsm4(Bh[nb], ad);
                ldsm4(Bl[nb], ad + 10240);
            }
            #pragma unroll
            for (int mf = 0; mf < 4; mf++)
                #pragma unroll
                for (int j = 0; j < 4; j++) {
                    uint32_t b0h = Bh[j >> 1][(j & 1) * 2], b1h = Bh[j >> 1][(j & 1) * 2 + 1];
                    uint32_t b0l = Bl[j >> 1][(j & 1) * 2], b1l = Bl[j >> 1][(j & 1) * 2 + 1];
                    mma16816(acc[mf][j], Ah[mf], b0h, b1h);
                    mma16816(acc[mf][j], Ah[mf], b0l, b1l);
                    mma16816(acc[mf][j], Al[mf], b0h, b1h);
                }
        }
        __syncthreads();
        if (c + 1 < nc) {
            char* st = sm + ((c + 1) & 1) * NT_STAGE;
            #pragma unroll
            for (int rb = 0; rb < 4; rb++) {
                uint2 hi, lo;
                int off = (lr + rb * 32) * 80 + lc * 2;
                split4(va[rb], hi, lo);
                *(uint2*)(st + off) = hi; *(uint2*)(st + 10240 + off) = lo;
                split4(vb[rb], hi, lo);
                *(uint2*)(st + 20480 + off) = hi; *(uint2*)(st + 30720 + off) = lo;
            }
        }
    }
}

// ===================== QKV projection (fused 3-way via blockIdx.z) =====================
__global__ void __launch_bounds__(256, 2) qkv_kernel(
    const float* __restrict__ x,
    const float* __restrict__ Wq, const float* __restrict__ Wk, const float* __restrict__ Wv,
    float* __restrict__ Qp, float* __restrict__ Kp, float* __restrict__ Vp)
{
    extern __shared__ char sm[];
    const float* W = (blockIdx.z == 0) ? Wq : (blockIdx.z == 1) ? Wk : Wv;
    float* outp    = (blockIdx.z == 0) ? Qp : (blockIdx.z == 1) ? Kp : Vp;

    float acc[4][4][4] = {};
    const int tileM = blockIdx.y * 128, tileN = blockIdx.x * 128;
    gemm_nt_mma(x + (size_t)tileM * DMODEL, DMODEL,
                W + (size_t)tileN * DMODEL, DMODEL, DMODEL, sm, acc);

    const int lane = threadIdx.x & 31, wid = threadIdx.x >> 5;
    const int h = blockIdx.x;
    #pragma unroll
    for (int mf = 0; mf < 4; mf++) {
        int row = tileM + (wid >> 2) * 64 + mf * 16 + (lane >> 2);
        #pragma unroll
        for (int j = 0; j < 4; j++) {
            int e = (wid & 3) * 32 + j * 8 + (lane & 3) * 2;
            int b0 = row >> 11, ns0 = row & 2047;
            float* d0 = outp + (((size_t)(b0 * NHEADS + h) * SEQ + ns0) * DH + e);
            *(float2*)d0 = make_float2(acc[mf][j][0], acc[mf][j][1]);
            int r1 = row + 8;
            int b1 = r1 >> 11, ns1 = r1 & 2047;
            float* d1 = outp + (((size_t)(b1 * NHEADS + h) * SEQ + ns1) * DH + e);
            *(float2*)d1 = make_float2(acc[mf][j][2], acc[mf][j][3]);
        }
    }
}

// ===================== scores: S = Q K^T + AP, masked -> g_A (always) =====================
__global__ void __launch_bounds__(256, 2) scores_kernel(
    const float* __restrict__ Q, const float* __restrict__ Km,
    const int* __restrict__ mask, const float* __restrict__ AP,
    float* __restrict__ Abuf)
{
    extern __shared__ char sm[];
    float acc[4][4][4] = {};
    const int bh = blockIdx.z;
    const int b = bh >> 3;
    const size_t hb = (size_t)bh * SEQ * DH;
    const int tileM = blockIdx.y * 128, tileN = blockIdx.x * 128;
    gemm_nt_mma(Q + hb + (size_t)tileM * DH, DH,
                Km + hb + (size_t)tileN * DH, DH, DH, sm, acc);

    float* C = Abuf + (size_t)bh * SEQ * SEQ;
    const int lane = threadIdx.x & 31, wid = threadIdx.x >> 5;
    const int* mb = mask + b * SEQ;
    #pragma unroll
    for (int mf = 0; mf < 4; mf++) {
        int r0 = tileM + (wid >> 2) * 64 + mf * 16 + (lane >> 2);
        int r1 = r0 + 8;
        int mr0 = mb[r0], mr1 = mb[r1];
        #pragma unroll
        for (int j = 0; j < 4; j++) {
            int col = tileN + (wid & 3) * 32 + j * 8 + (lane & 3) * 2;
            int mc0 = mb[col], mc1 = mb[col + 1];
            const float* ap0 = AP + (size_t)r0 * SEQ + col;
            const float* ap1 = AP + (size_t)r1 * SEQ + col;
            float2 o0, o1;
            o0.x = (mr0 && mc0) ? acc[mf][j][0] + ap0[0] : NEG_INF;
            o0.y = (mr0 && mc1) ? acc[mf][j][1] + ap0[1] : NEG_INF;
            o1.x = (mr1 && mc0) ? acc[mf][j][2] + ap1[0] : NEG_INF;
            o1.y = (mr1 && mc1) ? acc[mf][j][3] + ap1[1] : NEG_INF;
            *(float2*)(C + (size_t)r0 * SEQ + col) = o0;
            *(float2*)(C + (size_t)r1 * SEQ + col) = o1;
        }
    }
}

// ===================== row stats: streaming (max, sumexp) per row =====================
__global__ void __launch_bounds__(256) rowstats_kernel(
    const float* __restrict__ Abuf, float2* __restrict__ stats)
{
    const int row = blockIdx.x;                       // bh*2048 + q
    const float4* rp = (const float4*)(Abuf + (size_t)row * SEQ);
    const int t = threadIdx.x;
    float4 u = rp[2 * t], w = rp[2 * t + 1];

    float m = fmaxf(fmaxf(fmaxf(u.x, u.y), fmaxf(u.z, u.w)),
                    fmaxf(fmaxf(w.x, w.y), fmaxf(w.z, w.w)));
    __shared__ float sdata[256];
    sdata[t] = m;
    __syncthreads();
    for (int s = 128; s > 0; s >>= 1) {
        if (t < s) sdata[t] = fmaxf(sdata[t], sdata[t + s]);
        __syncthreads();
    }
    const float mx = sdata[0];
    __syncthreads();

    float sum = __expf(u.x - mx) + __expf(u.y - mx) + __expf(u.z - mx) + __expf(u.w - mx)
              + __expf(w.x - mx) + __expf(w.y - mx) + __expf(w.z - mx) + __expf(w.w - mx);
    sdata[t] = sum;
    __syncthreads();
    for (int s = 128; s > 0; s >>= 1) {
        if (t < s) sdata[t] += sdata[t + s];
        __syncthreads();
    }
    if (t == 0) stats[row] = make_float2(mx, sdata[0]);
}

// ===================== y = A^T V with softmax applied at load ==========
// TT layout: A element (k=j, m=i); stage rows=32 k, 128 cols, pad 272B
#define TT_STAGE 34816
#define TT_SMEM (2 * TT_STAGE)

__device__ __forceinline__ float4 exp_norm4(float4 v, float mx, float inv) {
    v.x = __expf(v.x - mx) * inv;
    v.y = __expf(v.y - mx) * inv;
    v.z = __expf(v.z - mx) * inv;
    v.w = __expf(v.w - mx) * inv;
    return v;
}

__global__ void __launch_bounds__(256, 2) av_kernel(
    const float* __restrict__ V, const float* __restrict__ Abuf,
    const float2* __restrict__ stats,
    float* __restrict__ attOut, int hasAtt, float* __restrict__ Y)
{
    extern __shared__ char sm[];
    float acc[4][4][4] = {};
    const int bh = blockIdx.y;
    const int b = bh >> 3, h = bh & 7;
    const int tileM = blockIdx.x * 128;
    const float* Ag = Abuf + (size_t)bh * SEQ * SEQ + tileM;   // (k, m-local)
    const float* Bg = V + (size_t)bh * SEQ * DH;
    const float2* strow = stats + (size_t)bh * SEQ;
    float* attB = attOut + (size_t)b * SEQ * SEQ + tileM;
    const bool wAtt = (h == 7) && hasAtt;

    const int tid = threadIdx.x, lane = tid & 31, wid = tid >> 5;
    const int morg = (wid >> 2) * 64, norg = (wid & 3) * 32;
    const int kr = tid >> 5, cg = tid & 31;
    const uint32_t sbase = smem_u32(sm);
    const int nc = SEQ / 32;
    float4 va[4], vb[4];

    #pragma unroll
    for (int rb = 0; rb < 4; rb++) {
        int j = kr + rb * 8;
        float2 st = strow[j];
        float inv = 1.0f / st.y;
        float4 v = *(const float4*)(Ag + (size_t)j * SEQ + cg * 4);
        v = exp_norm4(v, st.x, inv);
        if (wAtt) *(float4*)(attB + (size_t)j * SEQ + cg * 4) = v;
        va[rb] = v;
        vb[rb] = *(const float4*)(Bg + (size_t)j * DH + cg * 4);
    }
    {
        char* st = sm;
        #pragma unroll
        for (int rb = 0; rb < 4; rb++) {
            uint2 hi, lo;
            int off = (kr + rb * 8) * 272 + cg * 8;
            split4(va[rb], hi, lo);
            *(uint2*)(st + off) = hi; *(uint2*)(st + 8704 + off) = lo;
            split4(vb[rb], hi, lo);
            *(uint2*)(st + 17408 + off) = hi; *(uint2*)(st + 26112 + off) = lo;
        }
    }

    for (int c = 0; c < nc; c++) {
        __syncthreads();
        if (c + 1 < nc) {
            #pragma unroll
            for (int rb = 0; rb < 4; rb++) {
                int j = (c + 1) * 32 + kr + rb * 8;
                float2 st = strow[j];
                float inv = 1.0f / st.y;
                float4 v = *(const float4*)(Ag + (size_t)j * SEQ + cg * 4);
                v = exp_norm4(v, st.x, inv);
                if (wAtt) *(float4*)(attB + (size_t)j * SEQ + cg * 4) = v;
                va[rb] = v;
                vb[rb] = *(const float4*)(Bg + (size_t)j * DH + cg * 4);
            }
        }
        const uint32_t sst = sbase + (c & 1) * TT_STAGE;
        #pragma unroll
        for (int kh = 0; kh < 2; kh++) {
            uint32_t Ah[4][4], Al[4][4], Bh[2][4], Bl[2][4];
            #pragma unroll
            for (int mf = 0; mf < 4; mf++) {
                uint32_t krow = (lane & 7) + ((lane >> 4) << 3) + kh * 16;
                uint32_t ad = sst + krow * 272 + (((lane >> 3) & 1) << 4) + (morg + mf * 16) * 2;
                ldsm4_t(Ah[mf], ad);
                ldsm4_t(Al[mf], ad + 8704);
            }
            #pragma unroll
            for (int nb = 0; nb < 2; nb++) {
                uint32_t krow = (lane & 7) + (((lane >> 3) & 1) << 3) + kh * 16;
                uint32_t ad = sst + 17408 + krow * 272 + ((lane >> 4) << 4) + (norg + nb * 16) * 2;
                ldsm4_t(Bh[nb], ad);
                ldsm4_t(Bl[nb], ad + 8704);
            }
            #pragma unroll
            for (int mf = 0; mf < 4; mf++)
                #pragma unroll
                for (int j = 0; j < 4; j++) {
                    uint32_t b0h = Bh[j >> 1][(j & 1) * 2], b1h = Bh[j >> 1][(j & 1) * 2 + 1];
                    uint32_t b0l = Bl[j >> 1][(j & 1) * 2], b1l = Bl[j >> 1][(j & 1) * 2 + 1];
                    mma16816(acc[mf][j], Ah[mf], b0h, b1h);
                    mma16816(acc[mf][j], Ah[mf], b0l, b1l);
                    mma16816(acc[mf][j], Al[mf], b0h, b1h);
                }
        }
        __syncthreads();
        if (c + 1 < nc) {
            char* st = sm + ((c + 1) & 1) * TT_STAGE;
            #pragma unroll
            for (int rb = 0; rb < 4; rb++) {
                uint2 hi, lo;
                int off = (kr + rb * 8) * 272 + cg * 8;
                split4(va[rb], hi, lo);
                *(uint2*)(st + off) = hi; *(uint2*)(st + 8704 + off) = lo;
                split4(vb[rb], hi, lo);
                *(uint2*)(st + 17408 + off) = hi; *(uint2*)(st + 26112 + off) = lo;
            }
        }
    }

    const int lane2 = lane, wid2 = wid;
    #pragma unroll
    for (int mf = 0; mf < 4; mf++) {
        int i0 = tileM + (wid2 >> 2) * 64 + mf * 16 + (lane2 >> 2);
        #pragma unroll
        for (int j = 0; j < 4; j++) {
            int e = (wid2 & 3) * 32 + j * 8 + (lane2 & 3) * 2;
            float* d0 = Y + ((size_t)b * SEQ + i0) * DMODEL + h * DH + e;
            float* d1 = Y + ((size_t)b * SEQ + i0 + 8) * DMODEL + h * DH + e;
            *(float2*)d0 = make_float2(acc[mf][j][0], acc[mf][j][1]);
            *(float2*)d1 = make_float2(acc[mf][j][2], acc[mf][j][3]);
        }
    }
}

// ===================== out = Y * Wout^T =====================
__global__ void __launch_bounds__(256, 2) outproj_kernel(
    const float* __restrict__ Y, const float* __restrict__ Wout, float* __restrict__ out)
{
    extern __shared__ char sm[];
    float acc[4][4][4] = {};
    const int tileM = blockIdx.y * 128, tileN = blockIdx.x * 128;
    gemm_nt_mma(Y + (size_t)tileM * DMODEL, DMODEL,
                Wout + (size_t)tileN * DMODEL, DMODEL, DMODEL, sm, acc);

    const int lane = threadIdx.x & 31, wid = threadIdx.x >> 5;
    #pragma unroll
    for (int mf = 0; mf < 4; mf++) {
        int row = tileM + (wid >> 2) * 64 + mf * 16 + (lane >> 2);
        #pragma unroll
        for (int j = 0; j < 4; j++) {
            int col = tileN + (wid & 3) * 32 + j * 8 + (lane & 3) * 2;
            *(float2*)(out + (size_t)row * DMODEL + col) =
                make_float2(acc[mf][j][0], acc[mf][j][1]);
            *(float2*)(out + (size_t)(row + 8) * DMODEL + col) =
                make_float2(acc[mf][j][2], acc[mf][j][3]);
        }
    }
}

// ===================== AP table =====================
__global__ void ap_kernel(float* __restrict__ AP) {
    int idx = blockIdx.x * blockDim.x + threadIdx.x;
    const int total = SEQ * (SEQ / 2);
    if (idx >= total) return;
    int p = idx / (SEQ / 2);
    int i = idx % (SEQ / 2);
    float denom = powf(10000.0f, (2.0f * (float)i) / 1024.0f);
    float angle = (float)p / denom;
    float s, c;
    sincosf(angle, &s, &c);
    AP[(size_t)p * SEQ + 2 * i]     = s;
    AP[(size_t)p * SEQ + 2 * i + 1] = c;
}

// ===================== launch =====================
extern "C" void kernel_launch(void* const* d_in, const int* in_sizes, int n_in,
                              void* d_out, int out_size) {
    const float* x    = (const float*)d_in[0];
    const int*   mask = (const int*)  d_in[1];
    const float* Wq   = (const float*)d_in[2];
    const float* Wk   = (const float*)d_in[3];
    const float* Wv   = (const float*)d_in[4];
    const float* Wout = (const float*)d_in[5];
    float* out = (float*)d_out;

    const long long outElems = (long long)BSZ * SEQ * DMODEL;
    const long long attElems = (long long)BSZ * SEQ * SEQ;
    int hasAtt = ((long long)out_size >= outElems + attElems) ? 1 : 0;
    float* attOut = out + outElems;

    float *Qp, *Kp, *Vp, *APp, *Ap, *Yp;
    float2* Sp;
    cudaGetSymbolAddress((void**)&Qp,  g_Q);
    cudaGetSymbolAddress((void**)&Kp,  g_K);
    cudaGetSymbolAddress((void**)&Vp,  g_V);
    cudaGetSymbolAddress((void**)&APp, g_AP);
    cudaGetSymbolAddress((void**)&Ap,  g_A);
    cudaGetSymbolAddress((void**)&Sp,  g_stats);
    cudaGetSymbolAddress((void**)&Yp,  g_Y);

    cudaFuncSetAttribute(qkv_kernel,     cudaFuncAttributeMaxDynamicSharedMemorySize, NT_SMEM);
    cudaFuncSetAttribute(scores_kernel,  cudaFuncAttributeMaxDynamicSharedMemorySize, NT_SMEM);
    cudaFuncSetAttribute(outproj_kernel, cudaFuncAttributeMaxDynamicSharedMemorySize, NT_SMEM);
    cudaFuncSetAttribute(av_kernel,      cudaFuncAttributeMaxDynamicSharedMemorySize, TT_SMEM);

    // 1. AP table
    {
        int total = SEQ * (SEQ / 2);
        ap_kernel<<<(total + 255) / 256, 256>>>(APp);
    }
    // 2. Q/K/V projections, one launch
    {
        dim3 g(DMODEL / 128, (BSZ * SEQ) / 128, 3);
        qkv_kernel<<<g, 256, NT_SMEM>>>(x, Wq, Wk, Wv, Qp, Kp, Vp);
    }
    // 3. scores -> g_A
    {
        dim3 g(SEQ / 128, SEQ / 128, BSZ * NHEADS);
        scores_kernel<<<g, 256, NT_SMEM>>>(Qp, Kp, mask, APp, Ap);
    }
    // 4. row stats (streaming read of S)
    rowstats_kernel<<<BSZ * NHEADS * SEQ, 256>>>(Ap, Sp);
    // 5. y = A^T V with softmax applied at load (+ attOut for h==7)
    {
        dim3 g(SEQ / 128, BSZ * NHEADS);
        av_kernel<<<g, 256, TT_SMEM>>>(Vp, Ap, Sp, attOut, hasAtt, Yp);
    }
    // 6. out projection
    {
        dim3 g(DMODEL / 128, (BSZ * SEQ) / 128);
        outproj_kernel<<<g, 256, NT_SMEM>>>(Yp, Wout, out);
    }
}

// round 12
// speedup vs baseline: 1.3618x; 1.0535x over previous
#include <cuda_runtime.h>
#include <cuda_bf16.h>
#include <math.h>
#include <stdint.h>

#define BSZ 4
#define SEQ 2048
#define DMODEL 1024
#define NHEADS 8
#define DH 128
#define NEG_INF -1e9f

// ===================== static device scratch =====================
__device__ float  g_Q[BSZ * NHEADS * SEQ * DH];
__device__ float  g_K[BSZ * NHEADS * SEQ * DH];
__device__ float  g_V[BSZ * NHEADS * SEQ * DH];
__device__ float  g_AP[SEQ * SEQ];
__device__ float  g_A[(size_t)BSZ * NHEADS * SEQ * SEQ];
__device__ float2 g_part[(size_t)BSZ * NHEADS * SEQ * 16];   // per-row per-column-tile (max, sumexp)
__device__ float2 g_stats[BSZ * NHEADS * SEQ];
__device__ float  g_Y[BSZ * SEQ * DMODEL];

// ===================== helpers =====================
__device__ __forceinline__ uint32_t smem_u32(const void* p) {
    uint32_t a;
    asm("{ .reg .u64 t; cvta.to.shared.u64 t, %1; cvt.u32.u64 %0, t; }" : "=r"(a) : "l"(p));
    return a;
}
__device__ __forceinline__ void ldsm4(uint32_t* r, uint32_t addr) {
    asm volatile("ldmatrix.sync.aligned.m8n8.x4.shared.b16 {%0,%1,%2,%3}, [%4];"
        : "=r"(r[0]), "=r"(r[1]), "=r"(r[2]), "=r"(r[3]) : "r"(addr));
}
__device__ __forceinline__ void ldsm4_t(uint32_t* r, uint32_t addr) {
    asm volatile("ldmatrix.sync.aligned.m8n8.x4.trans.shared.b16 {%0,%1,%2,%3}, [%4];"
        : "=r"(r[0]), "=r"(r[1]), "=r"(r[2]), "=r"(r[3]) : "r"(addr));
}
__device__ __forceinline__ void mma16816(float* c, const uint32_t* a, uint32_t b0, uint32_t b1) {
    asm volatile("mma.sync.aligned.m16n8k16.row.col.f32.bf16.bf16.f32 "
        "{%0,%1,%2,%3}, {%4,%5,%6,%7}, {%8,%9}, {%0,%1,%2,%3};"
        : "+f"(c[0]), "+f"(c[1]), "+f"(c[2]), "+f"(c[3])
        : "r"(a[0]), "r"(a[1]), "r"(a[2]), "r"(a[3]), "r"(b0), "r"(b1));
}
__device__ __forceinline__ void split4(float4 v, uint2& hi, uint2& lo) {
    __nv_bfloat162 h0 = __floats2bfloat162_rn(v.x, v.y);
    __nv_bfloat162 h1 = __floats2bfloat162_rn(v.z, v.w);
    __nv_bfloat162 l0 = __floats2bfloat162_rn(v.x - __bfloat162float(h0.x),
                                              v.y - __bfloat162float(h0.y));
    __nv_bfloat162 l1 = __floats2bfloat162_rn(v.z - __bfloat162float(h1.x),
                                              v.w - __bfloat162float(h1.y));
    hi.x = *(uint32_t*)&h0; hi.y = *(uint32_t*)&h1;
    lo.x = *(uint32_t*)&l0; lo.y = *(uint32_t*)&l1;
}

// ===================== NT mainloop (A[m][k], B[n][k], fp32 -> bf16x3 mma) ==============
#define NT_STAGE 40960
#define NT_SMEM (2 * NT_STAGE)

__device__ __forceinline__ void gemm_nt_mma(
    const float* __restrict__ Ag, int lda,
    const float* __restrict__ Bg, int ldb,
    int K, char* sm, float (&acc)[4][4][4])
{
    const int tid = threadIdx.x, lane = tid & 31, wid = tid >> 5;
    const int morg = (wid >> 2) * 64, norg = (wid & 3) * 32;
    const int lr = tid >> 3, lc = (tid & 7) << 2;
    const uint32_t sbase = smem_u32(sm);
    const int nc = K / 32;
    float4 va[4], vb[4];

    #pragma unroll
    for (int rb = 0; rb < 4; rb++) {
        va[rb] = *(const float4*)(Ag + (size_t)(lr + rb * 32) * lda + lc);
        vb[rb] = *(const float4*)(Bg + (size_t)(lr + rb * 32) * ldb + lc);
    }
    {
        char* st = sm;
        #pragma unroll
        for (int rb = 0; rb < 4; rb++) {
            uint2 hi, lo;
            int off = (lr + rb * 32) * 80 + lc * 2;
            split4(va[rb], hi, lo);
            *(uint2*)(st + off) = hi; *(uint2*)(st + 10240 + off) = lo;
            split4(vb[rb], hi, lo);
            *(uint2*)(st + 20480 + off) = hi; *(uint2*)(st + 30720 + off) = lo;
        }
    }

    for (int c = 0; c < nc; c++) {
        __syncthreads();
        if (c + 1 < nc) {
            #pragma unroll
            for (int rb = 0; rb < 4; rb++) {
                va[rb] = *(const float4*)(Ag + (size_t)(lr + rb * 32) * lda + (c + 1) * 32 + lc);
                vb[rb] = *(const float4*)(Bg + (size_t)(lr + rb * 32) * ldb + (c + 1) * 32 + lc);
            }
        }
        const uint32_t sst = sbase + (c & 1) * NT_STAGE;
        #pragma unroll
        for (int kh = 0; kh < 2; kh++) {
            uint32_t Ah[4][4], Al[4][4], Bh[2][4], Bl[2][4];
            #pragma unroll
            for (int mf = 0; mf < 4; mf++) {
                uint32_t r = morg + mf * 16 + (lane & 15);
                uint32_t ad = sst + r * 80 + ((lane >> 4) << 4) + kh * 32;
                ldsm4(Ah[mf], ad);
                ldsm4(Al[mf], ad + 10240);
            }
            #pragma unroll
            for (int nb = 0; nb < 2; nb++) {
                uint32_t r = norg + nb * 16 + (lane & 7) + ((lane >> 4) << 3);
                uint32_t ad = sst + 20480 + r * 80 + (((lane >> 3) & 1) << 4) + kh * 32;
                ldsm4(Bh[nb], ad);
                ldsm4(Bl[nb], ad + 10240);
            }
            #pragma unroll
            for (int mf = 0; mf < 4; mf++)
                #pragma unroll
                for (int j = 0; j < 4; j++) {
                    uint32_t b0h = Bh[j >> 1][(j & 1) * 2], b1h = Bh[j >> 1][(j & 1) * 2 + 1];
                    uint32_t b0l = Bl[j >> 1][(j & 1) * 2], b1l = Bl[j >> 1][(j & 1) * 2 + 1];
                    mma16816(acc[mf][j], Ah[mf], b0h, b1h);
                    mma16816(acc[mf][j], Ah[mf], b0l, b1l);
                    mma16816(acc[mf][j], Al[mf], b0h, b1h);
                }
        }
        __syncthreads();
        if (c + 1 < nc) {
            char* st = sm + ((c + 1) & 1) * NT_STAGE;
            #pragma unroll
            for (int rb = 0; rb < 4; rb++) {
                uint2 hi, lo;
                int off = (lr + rb * 32) * 80 + lc * 2;
                split4(va[rb], hi, lo);
                *(uint2*)(st + off) = hi; *(uint2*)(st + 10240 + off) = lo;
                split4(vb[rb], hi, lo);
                *(uint2*)(st + 20480 + off) = hi; *(uint2*)(st + 30720 + off) = lo;
            }
        }
    }
}

// ===================== QKV projection (fused 3-way via blockIdx.z) =====================
__global__ void __launch_bounds__(256, 2) qkv_kernel(
    const float* __restrict__ x,
    const float* __restrict__ Wq, const float* __restrict__ Wk, const float* __restrict__ Wv,
    float* __restrict__ Qp, float* __restrict__ Kp, float* __restrict__ Vp)
{
    extern __shared__ char sm[];
    const float* W = (blockIdx.z == 0) ? Wq : (blockIdx.z == 1) ? Wk : Wv;
    float* outp    = (blockIdx.z == 0) ? Qp : (blockIdx.z == 1) ? Kp : Vp;

    float acc[4][4][4] = {};
    const int tileM = blockIdx.y * 128, tileN = blockIdx.x * 128;
    gemm_nt_mma(x + (size_t)tileM * DMODEL, DMODEL,
                W + (size_t)tileN * DMODEL, DMODEL, DMODEL, sm, acc);

    const int lane = threadIdx.x & 31, wid = threadIdx.x >> 5;
    const int h = blockIdx.x;
    #pragma unroll
    for (int mf = 0; mf < 4; mf++) {
        int row = tileM + (wid >> 2) * 64 + mf * 16 + (lane >> 2);
        #pragma unroll
        for (int j = 0; j < 4; j++) {
            int e = (wid & 3) * 32 + j * 8 + (lane & 3) * 2;
            int b0 = row >> 11, ns0 = row & 2047;
            float* d0 = outp + (((size_t)(b0 * NHEADS + h) * SEQ + ns0) * DH + e);
            *(float2*)d0 = make_float2(acc[mf][j][0], acc[mf][j][1]);
            int r1 = row + 8;
            int b1 = r1 >> 11, ns1 = r1 & 2047;
            float* d1 = outp + (((size_t)(b1 * NHEADS + h) * SEQ + ns1) * DH + e);
            *(float2*)d1 = make_float2(acc[mf][j][2], acc[mf][j][3]);
        }
    }
}

// ===================== scores: S = Q K^T + AP, masked -> g_A ; partial row stats ==========
__global__ void __launch_bounds__(256, 2) scores_kernel(
    const float* __restrict__ Q, const float* __restrict__ Km,
    const int* __restrict__ mask, const float* __restrict__ AP,
    float* __restrict__ Abuf, float2* __restrict__ part)
{
    extern __shared__ char sm[];
    float acc[4][4][4] = {};
    const int bh = blockIdx.z;
    const int b = bh >> 3;
    const size_t hb = (size_t)bh * SEQ * DH;
    const int tileM = blockIdx.y * 128, tileN = blockIdx.x * 128;
    gemm_nt_mma(Q + hb + (size_t)tileM * DH, DH,
                Km + hb + (size_t)tileN * DH, DH, DH, sm, acc);

    float* C = Abuf + (size_t)bh * SEQ * SEQ;
    const int tid = threadIdx.x, lane = tid & 31, wid = tid >> 5;
    const int morg = (wid >> 2) * 64, norg = (wid & 3) * 32;
    const int* mb = mask + b * SEQ;
    float2* smst = (float2*)sm;   // [8 warps][64 rows] over dead NT stage

    #pragma unroll
    for (int mf = 0; mf < 4; mf++) {
        int rl0 = morg + mf * 16 + (lane >> 2);
        int rl1 = rl0 + 8;
        int r0 = tileM + rl0, r1 = tileM + rl1;
        int mr0 = mb[r0], mr1 = mb[r1];
        float tm0 = -1e38f, ts0 = 0.f, tm1 = -1e38f, ts1 = 0.f;
        #pragma unroll
        for (int j = 0; j < 4; j++) {
            int col = tileN + norg + j * 8 + (lane & 3) * 2;
            int mc0 = mb[col], mc1 = mb[col + 1];
            const float* ap0 = AP + (size_t)r0 * SEQ + col;
            const float* ap1 = AP + (size_t)r1 * SEQ + col;
            float2 o0, o1;
            o0.x = (mr0 && mc0) ? acc[mf][j][0] + ap0[0] : NEG_INF;
            o0.y = (mr0 && mc1) ? acc[mf][j][1] + ap0[1] : NEG_INF;
            o1.x = (mr1 && mc0) ? acc[mf][j][2] + ap1[0] : NEG_INF;
            o1.y = (mr1 && mc1) ? acc[mf][j][3] + ap1[1] : NEG_INF;
            *(float2*)(C + (size_t)r0 * SEQ + col) = o0;
            *(float2*)(C + (size_t)r1 * SEQ + col) = o1;
            // online per-row stats
            float mx0 = fmaxf(tm0, fmaxf(o0.x, o0.y));
            ts0 = ts0 * __expf(tm0 - mx0) + __expf(o0.x - mx0) + __expf(o0.y - mx0);
            tm0 = mx0;
            float mx1 = fmaxf(tm1, fmaxf(o1.x, o1.y));
            ts1 = ts1 * __expf(tm1 - mx1) + __expf(o1.x - mx1) + __expf(o1.y - mx1);
            tm1 = mx1;
        }
        // quad merge (lanes sharing a row differ in lane&3)
        #pragma unroll
        for (int dx = 1; dx <= 2; dx <<= 1) {
            float om = __shfl_xor_sync(0xffffffff, tm0, dx);
            float os = __shfl_xor_sync(0xffffffff, ts0, dx);
            float M = fmaxf(tm0, om);
            ts0 = ts0 * __expf(tm0 - M) + os * __expf(om - M);
            tm0 = M;
            om = __shfl_xor_sync(0xffffffff, tm1, dx);
            os = __shfl_xor_sync(0xffffffff, ts1, dx);
            M = fmaxf(tm1, om);
            ts1 = ts1 * __expf(tm1 - M) + os * __expf(om - M);
            tm1 = M;
        }
        if ((lane & 3) == 0) {
            int base = wid * 64 + mf * 16 + (lane >> 2);
            smst[base]     = make_float2(tm0, ts0);
            smst[base + 8] = make_float2(tm1, ts1);
        }
    }
    __syncthreads();
    if (tid < 128) {
        int grp = tid >> 6;        // 0: warps 0-3 (rows 0-63), 1: warps 4-7 (rows 64-127)
        int rl = tid & 63;
        float M = -1e38f, S = 0.f;
        #pragma unroll
        for (int w = 0; w < 4; w++) {
            float2 p = smst[(grp * 4 + w) * 64 + rl];
            float Mn = fmaxf(M, p.x);
            S = S * __expf(M - Mn) + p.y * __expf(p.x - Mn);
            M = Mn;
        }
        part[((size_t)bh * SEQ + tileM + grp * 64 + rl) * 16 + blockIdx.x] = make_float2(M, S);
    }
}

// ===================== merge partial stats (16 tiles -> 1 per row) =====================
__global__ void __launch_bounds__(256) statsmerge_kernel(
    const float2* __restrict__ part, float2* __restrict__ stats)
{
    int row = blockIdx.x * blockDim.x + threadIdx.x;
    if (row >= BSZ * NHEADS * SEQ) return;
    const float2* p = part + (size_t)row * 16;
    float M = -1e38f, S = 0.f;
    #pragma unroll
    for (int t = 0; t < 16; t++) {
        float2 q = p[t];
        float Mn = fmaxf(M, q.x);
        S = S * __expf(M - Mn) + q.y * __expf(q.x - Mn);
        M = Mn;
    }
    stats[row] = make_float2(M, S);
}

// ===================== y = A^T V with softmax applied at load ==========
#define TT_STAGE 34816
#define TT_SMEM (2 * TT_STAGE)

__device__ __forceinline__ float4 exp_norm4(float4 v, float mx, float inv) {
    v.x = __expf(v.x - mx) * inv;
    v.y = __expf(v.y - mx) * inv;
    v.z = __expf(v.z - mx) * inv;
    v.w = __expf(v.w - mx) * inv;
    return v;
}

__global__ void __launch_bounds__(256, 2) av_kernel(
    const float* __restrict__ V, const float* __restrict__ Abuf,
    const float2* __restrict__ stats,
    float* __restrict__ attOut, int hasAtt, float* __restrict__ Y)
{
    extern __shared__ char sm[];
    float acc[4][4][4] = {};
    const int bh = blockIdx.y;
    const int b = bh >> 3, h = bh & 7;
    const int tileM = blockIdx.x * 128;
    const float* Ag = Abuf + (size_t)bh * SEQ * SEQ + tileM;
    const float* Bg = V + (size_t)bh * SEQ * DH;
    const float2* strow = stats + (size_t)bh * SEQ;
    float* attB = attOut + (size_t)b * SEQ * SEQ + tileM;
    const bool wAtt = (h == 7) && hasAtt;

    const int tid = threadIdx.x, lane = tid & 31, wid = tid >> 5;
    const int morg = (wid >> 2) * 64, norg = (wid & 3) * 32;
    const int kr = tid >> 5, cg = tid & 31;
    const uint32_t sbase = smem_u32(sm);
    const int nc = SEQ / 32;
    float4 va[4], vb[4];

    #pragma unroll
    for (int rb = 0; rb < 4; rb++) {
        int j = kr + rb * 8;
        float2 st = strow[j];
        float inv = 1.0f / st.y;
        float4 v = *(const float4*)(Ag + (size_t)j * SEQ + cg * 4);
        v = exp_norm4(v, st.x, inv);
        if (wAtt) *(float4*)(attB + (size_t)j * SEQ + cg * 4) = v;
        va[rb] = v;
        vb[rb] = *(const float4*)(Bg + (size_t)j * DH + cg * 4);
    }
    {
        char* st = sm;
        #pragma unroll
        for (int rb = 0; rb < 4; rb++) {
            uint2 hi, lo;
            int off = (kr + rb * 8) * 272 + cg * 8;
            split4(va[rb], hi, lo);
            *(uint2*)(st + off) = hi; *(uint2*)(st + 8704 + off) = lo;
            split4(vb[rb], hi, lo);
            *(uint2*)(st + 17408 + off) = hi; *(uint2*)(st + 26112 + off) = lo;
        }
    }

    for (int c = 0; c < nc; c++) {
        __syncthreads();
        if (c + 1 < nc) {
            #pragma unroll
            for (int rb = 0; rb < 4; rb++) {
                int j = (c + 1) * 32 + kr + rb * 8;
                float2 st = strow[j];
                float inv = 1.0f / st.y;
                float4 v = *(const float4*)(Ag + (size_t)j * SEQ + cg * 4);
                v = exp_norm4(v, st.x, inv);
                if (wAtt) *(float4*)(attB + (size_t)j * SEQ + cg * 4) = v;
                va[rb] = v;
                vb[rb] = *(const float4*)(Bg + (size_t)j * DH + cg * 4);
            }
        }
        const uint32_t sst = sbase + (c & 1) * TT_STAGE;
        #pragma unroll
        for (int kh = 0; kh < 2; kh++) {
            uint32_t Ah[4][4], Al[4][4], Bh[2][4], Bl[2][4];
            #pragma unroll
            for (int mf = 0; mf < 4; mf++) {
                uint32_t krow = (lane & 7) + ((lane >> 4) << 3) + kh * 16;
                uint32_t ad = sst + krow * 272 + (((lane >> 3) & 1) << 4) + (morg + mf * 16) * 2;
                ldsm4_t(Ah[mf], ad);
                ldsm4_t(Al[mf], ad + 8704);
            }
            #pragma unroll
            for (int nb = 0; nb < 2; nb++) {
                uint32_t krow = (lane & 7) + (((lane >> 3) & 1) << 3) + kh * 16;
                uint32_t ad = sst + 17408 + krow * 272 + ((lane >> 4) << 4) + (norg + nb * 16) * 2;
                ldsm4_t(Bh[nb], ad);
                ldsm4_t(Bl[nb], ad + 8704);
            }
            #pragma unroll
            for (int mf = 0; mf < 4; mf++)
                #pragma unroll
                for (int j = 0; j < 4; j++) {
                    uint32_t b0h = Bh[j >> 1][(j & 1) * 2], b1h = Bh[j >> 1][(j & 1) * 2 + 1];
                    uint32_t b0l = Bl[j >> 1][(j & 1) * 2], b1l = Bl[j >> 1][(j & 1) * 2 + 1];
                    mma16816(acc[mf][j], Ah[mf], b0h, b1h);
                    mma16816(acc[mf][j], Ah[mf], b0l, b1l);
                    mma16816(acc[mf][j], Al[mf], b0h, b1h);
                }
        }
        __syncthreads();
        if (c + 1 < nc) {
            char* st = sm + ((c + 1) & 1) * TT_STAGE;
            #pragma unroll
            for (int rb = 0; rb < 4; rb++) {
                uint2 hi, lo;
                int off = (kr + rb * 8) * 272 + cg * 8;
                split4(va[rb], hi, lo);
                *(uint2*)(st + off) = hi; *(uint2*)(st + 8704 + off) = lo;
                split4(vb[rb], hi, lo);
                *(uint2*)(st + 17408 + off) = hi; *(uint2*)(st + 26112 + off) = lo;
            }
        }
    }

    #pragma unroll
    for (int mf = 0; mf < 4; mf++) {
        int i0 = tileM + (wid >> 2) * 64 + mf * 16 + (lane >> 2);
        #pragma unroll
        for (int j = 0; j < 4; j++) {
            int e = (wid & 3) * 32 + j * 8 + (lane & 3) * 2;
            float* d0 = Y + ((size_t)b * SEQ + i0) * DMODEL + h * DH + e;
            float* d1 = Y + ((size_t)b * SEQ + i0 + 8) * DMODEL + h * DH + e;
            *(float2*)d0 = make_float2(acc[mf][j][0], acc[mf][j][1]);
            *(float2*)d1 = make_float2(acc[mf][j][2], acc[mf][j][3]);
        }
    }
}

// ===================== out = Y * Wout^T =====================
__global__ void __launch_bounds__(256, 2) outproj_kernel(
    const float* __restrict__ Y, const float* __restrict__ Wout, float* __restrict__ out)
{
    extern __shared__ char sm[];
    float acc[4][4][4] = {};
    const int tileM = blockIdx.y * 128, tileN = blockIdx.x * 128;
    gemm_nt_mma(Y + (size_t)tileM * DMODEL, DMODEL,
                Wout + (size_t)tileN * DMODEL, DMODEL, DMODEL, sm, acc);

    const int lane = threadIdx.x & 31, wid = threadIdx.x >> 5;
    #pragma unroll
    for (int mf = 0; mf < 4; mf++) {
        int row = tileM + (wid >> 2) * 64 + mf * 16 + (lane >> 2);
        #pragma unroll
        for (int j = 0; j < 4; j++) {
            int col = tileN + (wid & 3) * 32 + j * 8 + (lane & 3) * 2;
            *(float2*)(out + (size_t)row * DMODEL + col) =
                make_float2(acc[mf][j][0], acc[mf][j][1]);
            *(float2*)(out + (size_t)(row + 8) * DMODEL + col) =
                make_float2(acc[mf][j][2], acc[mf][j][3]);
        }
    }
}

// ===================== AP table =====================
__global__ void ap_kernel(float* __restrict__ AP) {
    int idx = blockIdx.x * blockDim.x + threadIdx.x;
    const int total = SEQ * (SEQ / 2);
    if (idx >= total) return;
    int p = idx / (SEQ / 2);
    int i = idx % (SEQ / 2);
    float denom = powf(10000.0f, (2.0f * (float)i) / 1024.0f);
    float angle = (float)p / denom;
    float s, c;
    sincosf(angle, &s, &c);
    AP[(size_t)p * SEQ + 2 * i]     = s;
    AP[(size_t)p * SEQ + 2 * i + 1] = c;
}

// ===================== launch =====================
extern "C" void kernel_launch(void* const* d_in, const int* in_sizes, int n_in,
                              void* d_out, int out_size) {
    const float* x    = (const float*)d_in[0];
    const int*   mask = (const int*)  d_in[1];
    const float* Wq   = (const float*)d_in[2];
    const float* Wk   = (const float*)d_in[3];
    const float* Wv   = (const float*)d_in[4];
    const float* Wout = (const float*)d_in[5];
    float* out = (float*)d_out;

    const long long outElems = (long long)BSZ * SEQ * DMODEL;
    const long long attElems = (long long)BSZ * SEQ * SEQ;
    int hasAtt = ((long long)out_size >= outElems + attElems) ? 1 : 0;
    float* attOut = out + outElems;

    float *Qp, *Kp, *Vp, *APp, *Ap, *Yp;
    float2 *Sp, *Pp;
    cudaGetSymbolAddress((void**)&Qp,  g_Q);
    cudaGetSymbolAddress((void**)&Kp,  g_K);
    cudaGetSymbolAddress((void**)&Vp,  g_V);
    cudaGetSymbolAddress((void**)&APp, g_AP);
    cudaGetSymbolAddress((void**)&Ap,  g_A);
    cudaGetSymbolAddress((void**)&Sp,  g_stats);
    cudaGetSymbolAddress((void**)&Pp,  g_part);
    cudaGetSymbolAddress((void**)&Yp,  g_Y);

    cudaFuncSetAttribute(qkv_kernel,     cudaFuncAttributeMaxDynamicSharedMemorySize, NT_SMEM);
    cudaFuncSetAttribute(scores_kernel,  cudaFuncAttributeMaxDynamicSharedMemorySize, NT_SMEM);
    cudaFuncSetAttribute(outproj_kernel, cudaFuncAttributeMaxDynamicSharedMemorySize, NT_SMEM);
    cudaFuncSetAttribute(av_kernel,      cudaFuncAttributeMaxDynamicSharedMemorySize, TT_SMEM);

    // 1. AP table
    {
        int total = SEQ * (SEQ / 2);
        ap_kernel<<<(total + 255) / 256, 256>>>(APp);
    }
    // 2. Q/K/V projections, one launch
    {
        dim3 g(DMODEL / 128, (BSZ * SEQ) / 128, 3);
        qkv_kernel<<<g, 256, NT_SMEM>>>(x, Wq, Wk, Wv, Qp, Kp, Vp);
    }
    // 3. scores -> g_A + per-tile row stats
    {
        dim3 g(SEQ / 128, SEQ / 128, BSZ * NHEADS);
        scores_kernel<<<g, 256, NT_SMEM>>>(Qp, Kp, mask, APp, Ap, Pp);
    }
    // 4. merge partial stats
    statsmerge_kernel<<<(BSZ * NHEADS * SEQ + 255) / 256, 256>>>(Pp, Sp);
    // 5. y = A^T V with softmax applied at load (+ attOut for h==7)
    {
        dim3 g(SEQ / 128, BSZ * NHEADS);
        av_kernel<<<g, 256, TT_SMEM>>>(Vp, Ap, Sp, attOut, hasAtt, Yp);
    }
    // 6. out projection
    {
        dim3 g(DMODEL / 128, (BSZ * SEQ) / 128);
        outproj_kernel<<<g, 256, NT_SMEM>>>(Yp, Wout, out);
    }
}